// round 14
// baseline (speedup 1.0000x reference)
#include <cuda_runtime.h>
#include <cuda_fp16.h>
#include <cstdint>

#define NE 8
#define NT 2048
#define ND 2048
#define NH 4096

// ---------------- scratch (static __device__, allocation-free) ----------------
__device__ __half g_x16[(long long)NE * NT * ND];
__device__ __half g_w1 [(long long)NE * ND * NH];
__device__ __half g_w3 [(long long)NE * ND * NH];
__device__ __half g_w2 [(long long)NE * NH * ND];
__device__ __half g_h16[(long long)NE * NT * NH];

// ---------------- PTX helpers (base-target sm_80+) ----------------
__device__ __forceinline__ void cp16s(uint32_t dst, const void* src) {
    asm volatile("cp.async.cg.shared.global [%0], [%1], 16;" :: "r"(dst), "l"(src));
}
__device__ __forceinline__ void ldsm4(uint32_t* r, uint32_t a) {
    asm volatile("ldmatrix.sync.aligned.m8n8.x4.shared.b16 {%0,%1,%2,%3}, [%4];"
                 : "=r"(r[0]), "=r"(r[1]), "=r"(r[2]), "=r"(r[3]) : "r"(a));
}
__device__ __forceinline__ void ldsm4t(uint32_t* r, uint32_t a) {
    asm volatile("ldmatrix.sync.aligned.m8n8.x4.trans.shared.b16 {%0,%1,%2,%3}, [%4];"
                 : "=r"(r[0]), "=r"(r[1]), "=r"(r[2]), "=r"(r[3]) : "r"(a));
}
__device__ __forceinline__ void mma16816(float* d, const uint32_t* a, const uint32_t* b) {
    asm volatile(
        "mma.sync.aligned.m16n8k16.row.col.f32.f16.f16.f32 "
        "{%0,%1,%2,%3}, {%4,%5,%6,%7}, {%8,%9}, {%0,%1,%2,%3};"
        : "+f"(d[0]), "+f"(d[1]), "+f"(d[2]), "+f"(d[3])
        : "r"(a[0]), "r"(a[1]), "r"(a[2]), "r"(a[3]), "r"(b[0]), "r"(b[1]));
}

// 8-element fp32 -> fp16 convert unit
__device__ __forceinline__ void conv8(const float4* __restrict__ src,
                                      __half2* __restrict__ dst, long long u) {
    float4 v0 = src[2 * u];
    float4 v1 = src[2 * u + 1];
    __half2 h[4];
    h[0] = __floats2half2_rn(v0.x, v0.y);
    h[1] = __floats2half2_rn(v0.z, v0.w);
    h[2] = __floats2half2_rn(v1.x, v1.y);
    h[3] = __floats2half2_rn(v1.z, v1.w);
    *(uint4*)(dst + 4 * u) = *(uint4*)h;
}

// ---------------- merged conversion: x, w1, w3 in one launch ----------------
__global__ void conv3_kernel(const float4* __restrict__ X, const float4* __restrict__ W1,
                             const float4* __restrict__ W3) {
    const long long UX = (long long)NE * NT * ND / 8;
    const long long UW = (long long)NE * ND * NH / 8;
    long long u = (long long)blockIdx.x * blockDim.x + threadIdx.x;
    if (u < UX)            conv8(X,  (__half2*)g_x16, u);
    else if (u < UX + UW)  conv8(W1, (__half2*)g_w1,  u - UX);
    else                   conv8(W3, (__half2*)g_w3,  u - UX - UW);
}

// ---------------- GEMM13 (fused): h = silu(x@w1) * (x@w3)  [+ piggybacked w2 conv] ----------------
// BM=128, BN=64, BK=64; 256 threads = 8 warps (2m x 4n), warp tile 64x16.
// SMEM: 3 slots x 32KB (A 16K | B1 8K | B3 8K) -> 2 CTAs/SM.
// blockIdx.z == NE plane: 1024 CTAs convert w2 fp32->fp16 (consumed by gemm2).
__global__ __launch_bounds__(256, 2)
void gemm13_fused(const __half* __restrict__ X, const __half* __restrict__ W1,
                  const __half* __restrict__ W3, __half* __restrict__ H,
                  const float4* __restrict__ W2f)
{
    if (blockIdx.z == NE) {
        const long long UW = (long long)NE * NH * ND / 8;
        const long long stride = (long long)gridDim.x * gridDim.y * blockDim.x;
        long long id = ((long long)blockIdx.y * gridDim.x + blockIdx.x) * blockDim.x
                       + threadIdx.x;
        for (long long u = id; u < UW; u += stride)
            conv8(W2f, (__half2*)g_w2, u);
        return;
    }

    extern __shared__ __align__(128) char smem[];
    const uint32_t sbase = (uint32_t)__cvta_generic_to_shared(smem);
    const int tid = threadIdx.x;
    const int e  = blockIdx.z;
    const int n0 = blockIdx.x * 64;
    const int m0 = blockIdx.y * 128;

    const __half* pA  = X  + (long long)e * NT * ND + (long long)m0 * ND;
    const __half* pB1 = W1 + (long long)e * ND * NH + n0;
    const __half* pB3 = W3 + (long long)e * ND * NH + n0;

    const int warp = tid >> 5, lane = tid & 31;
    const int wm = (warp & 1) * 64;
    const int wn = (warp >> 1) * 16;

    float acc1[4][2][4], acc3[4][2][4];
    #pragma unroll
    for (int i = 0; i < 4; i++)
        #pragma unroll
        for (int j = 0; j < 2; j++)
            #pragma unroll
            for (int r = 0; r < 4; r++) { acc1[i][j][r] = 0.f; acc3[i][j][r] = 0.f; }

    auto load_stage = [&](int slot, int k0) {
        const uint32_t sb = sbase + slot * 32768;
        #pragma unroll
        for (int i = 0; i < 4; i++) {
            int id = tid + i * 256;
            int row = id >> 3, c = id & 7;
            cp16s(sb + row * 128 + ((c ^ (row & 7)) << 4),
                  pA + (long long)row * ND + k0 + c * 8);
        }
        #pragma unroll
        for (int i = 0; i < 2; i++) {
            int id = tid + i * 256;
            int row = id >> 3, c = id & 7;
            long long go = (long long)(k0 + row) * NH + c * 8;
            uint32_t so = sb + 16384 + row * 128 + ((c ^ (row & 7)) << 4);
            cp16s(so,        pB1 + go);
            cp16s(so + 8192, pB3 + go);
        }
        asm volatile("cp.async.commit_group;" ::: "memory");
    };

    load_stage(0, 0);
    load_stage(1, 64);

    const int NKC = ND / 64;
    for (int ch = 0; ch < NKC; ch++) {
        asm volatile("cp.async.wait_group 1;" ::: "memory");
        __syncthreads();
        if (ch + 2 < NKC) load_stage((ch + 2) % 3, (ch + 2) * 64);
        else asm volatile("cp.async.commit_group;" ::: "memory");

        const uint32_t sb = sbase + (ch % 3) * 32768;
        #pragma unroll
        for (int ks = 0; ks < 4; ks++) {
            uint32_t av[4][4], b1[2][2], b3[2][2];
            #pragma unroll
            for (int mt = 0; mt < 4; mt++) {
                int row = wm + mt * 16 + (lane & 15);
                int cc  = ks * 2 + (lane >> 4);
                ldsm4(av[mt], sb + row * 128 + ((cc ^ (row & 7)) << 4));
            }
            {
                int kr = ks * 16 + (lane & 15);
                int nc = (wn >> 3) + (lane >> 4);
                uint32_t bd = sb + 16384 + kr * 128 + ((nc ^ (kr & 7)) << 4);
                uint32_t r[4];
                ldsm4t(r, bd);
                b1[0][0] = r[0]; b1[0][1] = r[1];
                b1[1][0] = r[2]; b1[1][1] = r[3];
                ldsm4t(r, bd + 8192);
                b3[0][0] = r[0]; b3[0][1] = r[1];
                b3[1][0] = r[2]; b3[1][1] = r[3];
            }
            #pragma unroll
            for (int mt = 0; mt < 4; mt++)
                #pragma unroll
                for (int nt = 0; nt < 2; nt++) {
                    mma16816(acc1[mt][nt], av[mt], b1[nt]);
                    mma16816(acc3[mt][nt], av[mt], b3[nt]);
                }
        }
    }

    #pragma unroll
    for (int mt = 0; mt < 4; mt++)
        #pragma unroll
        for (int nt = 0; nt < 2; nt++) {
            const int row = m0 + wm + mt * 16 + (lane >> 2);
            const int col = n0 + wn + nt * 8 + (lane & 3) * 2;
            const long long i0 = ((long long)e * NT + row) * NH + col;
            const long long i1 = i0 + 8LL * NH;
            const float a0 = acc1[mt][nt][0], a1 = acc1[mt][nt][1];
            const float a2 = acc1[mt][nt][2], a3 = acc1[mt][nt][3];
            const float v0 = acc3[mt][nt][0] * a0 / (1.f + __expf(-a0));
            const float v1 = acc3[mt][nt][1] * a1 / (1.f + __expf(-a1));
            const float v2 = acc3[mt][nt][2] * a2 / (1.f + __expf(-a2));
            const float v3 = acc3[mt][nt][3] * a3 / (1.f + __expf(-a3));
            *(__half2*)&H[i0] = __floats2half2_rn(v0, v1);
            *(__half2*)&H[i1] = __floats2half2_rn(v2, v3);
        }
}

// ---------------- GEMM2: out = h @ w2 (fp32 out) ----------------
// BM=128, BN=256, BK=64; 8 warps (2m x 4n), warp tile 64x64 -> 128B smem/HMMA.
// SMEM: 3 slots x 48KB (A 16K | B 32K) = 144KB -> 1 CTA/SM.
__global__ __launch_bounds__(256, 1)
void gemm2_out(const __half* __restrict__ Hm, const __half* __restrict__ W2,
               float* __restrict__ Out)
{
    extern __shared__ __align__(128) char smem[];
    const uint32_t sbase = (uint32_t)__cvta_generic_to_shared(smem);
    const int tid = threadIdx.x;
    const int e  = blockIdx.z;
    const int n0 = blockIdx.x * 256;
    const int m0 = blockIdx.y * 128;

    const __half* pA = Hm + (long long)e * NT * NH + (long long)m0 * NH;
    const __half* pB = W2 + (long long)e * NH * ND + n0;

    const int warp = tid >> 5, lane = tid & 31;
    const int wm = (warp & 1) * 64;      // 2 m-warps x 64 rows
    const int wn = (warp >> 1) * 64;     // 4 n-warps x 64 cols

    float acc[4][8][4];
    #pragma unroll
    for (int i = 0; i < 4; i++)
        #pragma unroll
        for (int j = 0; j < 8; j++)
            #pragma unroll
            for (int r = 0; r < 4; r++) acc[i][j][r] = 0.f;

    auto load_stage = [&](int slot, int k0) {
        const uint32_t sb = sbase + slot * 49152;
        #pragma unroll
        for (int i = 0; i < 4; i++) {          // A: 128 rows x 8 chunks of 16B
            int id = tid + i * 256;
            int row = id >> 3, c = id & 7;
            cp16s(sb + row * 128 + ((c ^ (row & 7)) << 4),
                  pA + (long long)row * NH + k0 + c * 8);
        }
        #pragma unroll
        for (int i = 0; i < 8; i++) {          // B: 64 rows x 32 chunks (512B rows)
            int id = tid + i * 256;
            int row = id >> 5, c = id & 31;
            cp16s(sb + 16384 + row * 512 + ((c ^ (row & 7)) << 4),
                  pB + (long long)(k0 + row) * ND + c * 8);
        }
        asm volatile("cp.async.commit_group;" ::: "memory");
    };

    load_stage(0, 0);
    load_stage(1, 64);

    const int NKC = NH / 64;
    for (int ch = 0; ch < NKC; ch++) {
        asm volatile("cp.async.wait_group 1;" ::: "memory");
        __syncthreads();
        if (ch + 2 < NKC) load_stage((ch + 2) % 3, (ch + 2) * 64);
        else asm volatile("cp.async.commit_group;" ::: "memory");

        const uint32_t sb = sbase + (ch % 3) * 49152;
        #pragma unroll
        for (int ks = 0; ks < 4; ks++) {
            uint32_t av[4][4], bv[8][2];
            #pragma unroll
            for (int mt = 0; mt < 4; mt++) {
                int row = wm + mt * 16 + (lane & 15);
                int cc  = ks * 2 + (lane >> 4);
                ldsm4(av[mt], sb + row * 128 + ((cc ^ (row & 7)) << 4));
            }
            #pragma unroll
            for (int np = 0; np < 4; np++) {   // 4 x ldsm4t cover 8 n8 tiles
                int kr = ks * 16 + (lane & 15);
                int nc = (wn >> 3) + np * 2 + (lane >> 4);
                uint32_t bd = sb + 16384 + kr * 512 + ((nc ^ (kr & 7)) << 4);
                uint32_t r[4];
                ldsm4t(r, bd);
                bv[np*2][0] = r[0]; bv[np*2][1] = r[1];
                bv[np*2+1][0] = r[2]; bv[np*2+1][1] = r[3];
            }
            #pragma unroll
            for (int mt = 0; mt < 4; mt++)
                #pragma unroll
                for (int nt = 0; nt < 8; nt++)
                    mma16816(acc[mt][nt], av[mt], bv[nt]);
        }
    }

    #pragma unroll
    for (int mt = 0; mt < 4; mt++)
        #pragma unroll
        for (int nt = 0; nt < 8; nt++) {
            const int row = m0 + wm + mt * 16 + (lane >> 2);
            const int col = n0 + wn + nt * 8 + (lane & 3) * 2;
            const long long i0 = ((long long)e * NT + row) * ND + col;
            const long long i1 = i0 + 8LL * ND;
            *(float2*)&Out[i0] = make_float2(acc[mt][nt][0], acc[mt][nt][1]);
            *(float2*)&Out[i1] = make_float2(acc[mt][nt][2], acc[mt][nt][3]);
        }
}

// ---------------- launch ----------------
// Inputs: x [E,T,D] fp32, w1 [E,D,H], w2 [E,H,D], w3 [E,D,H]. Output [E,T,D] fp32.
extern "C" void kernel_launch(void* const* d_in, const int* in_sizes, int n_in,
                              void* d_out, int out_size)
{
    const float* x  = (const float*)d_in[0];
    const float* w1 = (const float*)d_in[1];
    const float* w2 = (const float*)d_in[2];
    const float* w3 = (const float*)d_in[3];
    float* out = (float*)d_out;

    cudaFuncSetAttribute(gemm13_fused, cudaFuncAttributeMaxDynamicSharedMemorySize, 98304);
    cudaFuncSetAttribute(gemm2_out,    cudaFuncAttributeMaxDynamicSharedMemorySize, 147456);

    void *x16, *w1p, *w3p, *w2p, *h16;
    cudaGetSymbolAddress(&x16, g_x16);
    cudaGetSymbolAddress(&w1p, g_w1);
    cudaGetSymbolAddress(&w3p, g_w3);
    cudaGetSymbolAddress(&w2p, g_w2);
    cudaGetSymbolAddress(&h16, g_h16);

    // 1) merged conversion of x, w1, w3 (w2 converted inside gemm13's launch)
    const long long UX = (long long)NE * NT * ND / 8;
    const long long UW = (long long)NE * ND * NH / 8;
    conv3_kernel<<<(int)((UX + 2 * UW) / 256), 256>>>((const float4*)x, (const float4*)w1,
                                                      (const float4*)w3);

    // 2) gemm13 (+ w2 conversion plane at blockIdx.z == NE)
    gemm13_fused<<<dim3(NH / 64, NT / 128, NE + 1), 256, 98304>>>(
        (const __half*)x16, (const __half*)w1p, (const __half*)w3p, (__half*)h16,
        (const float4*)w2);

    // 3) out = h @ w2
    gemm2_out<<<dim3(ND / 256, NT / 128, NE), 256, 147456>>>(
        (const __half*)h16, (const __half*)w2p, out);
}

// round 15
// speedup vs baseline: 1.0291x; 1.0291x over previous
#include <cuda_runtime.h>
#include <cuda_fp16.h>
#include <cstdint>

#define NE 8
#define NT 2048
#define ND 2048
#define NH 4096

// ---------------- scratch (static __device__, allocation-free) ----------------
__device__ __half g_x16[(long long)NE * NT * ND];
__device__ __half g_w1 [(long long)NE * ND * NH];
__device__ __half g_w3 [(long long)NE * ND * NH];
__device__ __half g_w2 [(long long)NE * NH * ND];
__device__ __half g_h16[(long long)NE * NT * NH];

// ---------------- PTX helpers (base-target sm_80+) ----------------
__device__ __forceinline__ void cp16s(uint32_t dst, const void* src) {
    asm volatile("cp.async.cg.shared.global [%0], [%1], 16;" :: "r"(dst), "l"(src));
}
__device__ __forceinline__ void ldsm4(uint32_t* r, uint32_t a) {
    asm volatile("ldmatrix.sync.aligned.m8n8.x4.shared.b16 {%0,%1,%2,%3}, [%4];"
                 : "=r"(r[0]), "=r"(r[1]), "=r"(r[2]), "=r"(r[3]) : "r"(a));
}
__device__ __forceinline__ void ldsm4t(uint32_t* r, uint32_t a) {
    asm volatile("ldmatrix.sync.aligned.m8n8.x4.trans.shared.b16 {%0,%1,%2,%3}, [%4];"
                 : "=r"(r[0]), "=r"(r[1]), "=r"(r[2]), "=r"(r[3]) : "r"(a));
}
__device__ __forceinline__ void mma16816(float* d, const uint32_t* a, const uint32_t* b) {
    asm volatile(
        "mma.sync.aligned.m16n8k16.row.col.f32.f16.f16.f32 "
        "{%0,%1,%2,%3}, {%4,%5,%6,%7}, {%8,%9}, {%0,%1,%2,%3};"
        : "+f"(d[0]), "+f"(d[1]), "+f"(d[2]), "+f"(d[3])
        : "r"(a[0]), "r"(a[1]), "r"(a[2]), "r"(a[3]), "r"(b[0]), "r"(b[1]));
}

// 8-element fp32 -> fp16 convert unit
__device__ __forceinline__ void conv8(const float4* __restrict__ src,
                                      __half2* __restrict__ dst, long long u) {
    float4 v0 = src[2 * u];
    float4 v1 = src[2 * u + 1];
    __half2 h[4];
    h[0] = __floats2half2_rn(v0.x, v0.y);
    h[1] = __floats2half2_rn(v0.z, v0.w);
    h[2] = __floats2half2_rn(v1.x, v1.y);
    h[3] = __floats2half2_rn(v1.z, v1.w);
    *(uint4*)(dst + 4 * u) = *(uint4*)h;
}

// ---------------- merged conversion: x, w1, w3 in one launch ----------------
__global__ void conv3_kernel(const float4* __restrict__ X, const float4* __restrict__ W1,
                             const float4* __restrict__ W3) {
    const long long UX = (long long)NE * NT * ND / 8;
    const long long UW = (long long)NE * ND * NH / 8;
    long long u = (long long)blockIdx.x * blockDim.x + threadIdx.x;
    if (u < UX)            conv8(X,  (__half2*)g_x16, u);
    else if (u < UX + UW)  conv8(W1, (__half2*)g_w1,  u - UX);
    else                   conv8(W3, (__half2*)g_w3,  u - UX - UW);
}

// ---------------- GEMM13 (fused): h = silu(x@w1) * (x@w3)  [+ piggybacked w2 conv] ----------------
// BM=128, BN=64, BK=64; 256 threads = 8 warps (2m x 4n), warp tile 64x16.
// SMEM: 3 slots x 32KB (A 16K | B1 8K | B3 8K) -> 2 CTAs/SM.
// blockIdx.z == NE plane: 1024 CTAs convert w2 fp32->fp16 (consumed by gemm2).
__global__ __launch_bounds__(256, 2)
void gemm13_fused(const __half* __restrict__ X, const __half* __restrict__ W1,
                  const __half* __restrict__ W3, __half* __restrict__ H,
                  const float4* __restrict__ W2f)
{
    if (blockIdx.z == NE) {
        const long long UW = (long long)NE * NH * ND / 8;
        const long long stride = (long long)gridDim.x * gridDim.y * blockDim.x;
        long long id = ((long long)blockIdx.y * gridDim.x + blockIdx.x) * blockDim.x
                       + threadIdx.x;
        for (long long u = id; u < UW; u += stride)
            conv8(W2f, (__half2*)g_w2, u);
        return;
    }

    extern __shared__ __align__(128) char smem[];
    const uint32_t sbase = (uint32_t)__cvta_generic_to_shared(smem);
    const int tid = threadIdx.x;
    const int e  = blockIdx.z;
    const int n0 = blockIdx.x * 64;
    const int m0 = blockIdx.y * 128;

    const __half* pA  = X  + (long long)e * NT * ND + (long long)m0 * ND;
    const __half* pB1 = W1 + (long long)e * ND * NH + n0;
    const __half* pB3 = W3 + (long long)e * ND * NH + n0;

    const int warp = tid >> 5, lane = tid & 31;
    const int wm = (warp & 1) * 64;
    const int wn = (warp >> 1) * 16;

    float acc1[4][2][4], acc3[4][2][4];
    #pragma unroll
    for (int i = 0; i < 4; i++)
        #pragma unroll
        for (int j = 0; j < 2; j++)
            #pragma unroll
            for (int r = 0; r < 4; r++) { acc1[i][j][r] = 0.f; acc3[i][j][r] = 0.f; }

    auto load_stage = [&](int slot, int k0) {
        const uint32_t sb = sbase + slot * 32768;
        #pragma unroll
        for (int i = 0; i < 4; i++) {
            int id = tid + i * 256;
            int row = id >> 3, c = id & 7;
            cp16s(sb + row * 128 + ((c ^ (row & 7)) << 4),
                  pA + (long long)row * ND + k0 + c * 8);
        }
        #pragma unroll
        for (int i = 0; i < 2; i++) {
            int id = tid + i * 256;
            int row = id >> 3, c = id & 7;
            long long go = (long long)(k0 + row) * NH + c * 8;
            uint32_t so = sb + 16384 + row * 128 + ((c ^ (row & 7)) << 4);
            cp16s(so,        pB1 + go);
            cp16s(so + 8192, pB3 + go);
        }
        asm volatile("cp.async.commit_group;" ::: "memory");
    };

    load_stage(0, 0);
    load_stage(1, 64);

    const int NKC = ND / 64;
    for (int ch = 0; ch < NKC; ch++) {
        asm volatile("cp.async.wait_group 1;" ::: "memory");
        __syncthreads();
        if (ch + 2 < NKC) load_stage((ch + 2) % 3, (ch + 2) * 64);
        else asm volatile("cp.async.commit_group;" ::: "memory");

        const uint32_t sb = sbase + (ch % 3) * 32768;
        #pragma unroll
        for (int ks = 0; ks < 4; ks++) {
            uint32_t av[4][4], b1[2][2], b3[2][2];
            {   // B loads first: their latency overlaps the A-load issue sequence
                int kr = ks * 16 + (lane & 15);
                int nc = (wn >> 3) + (lane >> 4);
                uint32_t bd = sb + 16384 + kr * 128 + ((nc ^ (kr & 7)) << 4);
                uint32_t r[4];
                ldsm4t(r, bd);
                b1[0][0] = r[0]; b1[0][1] = r[1];
                b1[1][0] = r[2]; b1[1][1] = r[3];
                ldsm4t(r, bd + 8192);
                b3[0][0] = r[0]; b3[0][1] = r[1];
                b3[1][0] = r[2]; b3[1][1] = r[3];
            }
            #pragma unroll
            for (int mt = 0; mt < 4; mt++) {
                int row = wm + mt * 16 + (lane & 15);
                int cc  = ks * 2 + (lane >> 4);
                ldsm4(av[mt], sb + row * 128 + ((cc ^ (row & 7)) << 4));
            }
            #pragma unroll
            for (int mt = 0; mt < 4; mt++)
                #pragma unroll
                for (int nt = 0; nt < 2; nt++) {
                    mma16816(acc1[mt][nt], av[mt], b1[nt]);
                    mma16816(acc3[mt][nt], av[mt], b3[nt]);
                }
        }
    }

    #pragma unroll
    for (int mt = 0; mt < 4; mt++)
        #pragma unroll
        for (int nt = 0; nt < 2; nt++) {
            const int row = m0 + wm + mt * 16 + (lane >> 2);
            const int col = n0 + wn + nt * 8 + (lane & 3) * 2;
            const long long i0 = ((long long)e * NT + row) * NH + col;
            const long long i1 = i0 + 8LL * NH;
            const float a0 = acc1[mt][nt][0], a1 = acc1[mt][nt][1];
            const float a2 = acc1[mt][nt][2], a3 = acc1[mt][nt][3];
            const float v0 = acc3[mt][nt][0] * a0 / (1.f + __expf(-a0));
            const float v1 = acc3[mt][nt][1] * a1 / (1.f + __expf(-a1));
            const float v2 = acc3[mt][nt][2] * a2 / (1.f + __expf(-a2));
            const float v3 = acc3[mt][nt][3] * a3 / (1.f + __expf(-a3));
            *(__half2*)&H[i0] = __floats2half2_rn(v0, v1);
            *(__half2*)&H[i1] = __floats2half2_rn(v2, v3);
        }
}

// ---------------- GEMM2: out = h @ w2 (fp32 out) ----------------
// BM=128, BN=128, BK=64; 3 slots x 32KB = 96KB -> 2 CTAs/SM.
__global__ __launch_bounds__(256, 2)
void gemm2_out(const __half* __restrict__ Hm, const __half* __restrict__ W2,
               float* __restrict__ Out)
{
    extern __shared__ __align__(128) char smem[];
    const uint32_t sbase = (uint32_t)__cvta_generic_to_shared(smem);
    const int tid = threadIdx.x;
    const int e  = blockIdx.z;
    const int n0 = blockIdx.x * 128;
    const int m0 = blockIdx.y * 128;

    const __half* pA = Hm + (long long)e * NT * NH + (long long)m0 * NH;
    const __half* pB = W2 + (long long)e * NH * ND + n0;

    const int warp = tid >> 5, lane = tid & 31;
    const int wm = (warp & 1) * 64;
    const int wn = (warp >> 1) * 32;

    float acc[4][4][4];
    #pragma unroll
    for (int i = 0; i < 4; i++)
        #pragma unroll
        for (int j = 0; j < 4; j++)
            #pragma unroll
            for (int r = 0; r < 4; r++) acc[i][j][r] = 0.f;

    auto load_stage = [&](int slot, int k0) {
        const uint32_t sb = sbase + slot * 32768;
        #pragma unroll
        for (int i = 0; i < 4; i++) {
            int id = tid + i * 256;
            int row = id >> 3, c = id & 7;
            cp16s(sb + row * 128 + ((c ^ (row & 7)) << 4),
                  pA + (long long)row * NH + k0 + c * 8);
        }
        #pragma unroll
        for (int i = 0; i < 4; i++) {
            int id = tid + i * 256;
            int row = id >> 4, c = id & 15;
            cp16s(sb + 16384 + row * 256 + ((c ^ (row & 7)) << 4),
                  pB + (long long)(k0 + row) * ND + c * 8);
        }
        asm volatile("cp.async.commit_group;" ::: "memory");
    };

    load_stage(0, 0);
    load_stage(1, 64);

    const int NKC = NH / 64;
    for (int ch = 0; ch < NKC; ch++) {
        asm volatile("cp.async.wait_group 1;" ::: "memory");
        __syncthreads();
        if (ch + 2 < NKC) load_stage((ch + 2) % 3, (ch + 2) * 64);
        else asm volatile("cp.async.commit_group;" ::: "memory");

        const uint32_t sb = sbase + (ch % 3) * 32768;
        #pragma unroll
        for (int ks = 0; ks < 4; ks++) {
            uint32_t av[4][4], bv[4][2];
            #pragma unroll
            for (int np = 0; np < 2; np++) {   // B loads first
                int kr = ks * 16 + (lane & 15);
                int nc = (wn >> 3) + np * 2 + (lane >> 4);
                uint32_t bd = sb + 16384 + kr * 256 + ((nc ^ (kr & 7)) << 4);
                uint32_t r[4];
                ldsm4t(r, bd);
                bv[np*2][0] = r[0]; bv[np*2][1] = r[1];
                bv[np*2+1][0] = r[2]; bv[np*2+1][1] = r[3];
            }
            #pragma unroll
            for (int mt = 0; mt < 4; mt++) {
                int row = wm + mt * 16 + (lane & 15);
                int cc  = ks * 2 + (lane >> 4);
                ldsm4(av[mt], sb + row * 128 + ((cc ^ (row & 7)) << 4));
            }
            #pragma unroll
            for (int mt = 0; mt < 4; mt++)
                #pragma unroll
                for (int nt = 0; nt < 4; nt++)
                    mma16816(acc[mt][nt], av[mt], bv[nt]);
        }
    }

    #pragma unroll
    for (int mt = 0; mt < 4; mt++)
        #pragma unroll
        for (int nt = 0; nt < 4; nt++) {
            const int row = m0 + wm + mt * 16 + (lane >> 2);
            const int col = n0 + wn + nt * 8 + (lane & 3) * 2;
            const long long i0 = ((long long)e * NT + row) * ND + col;
            const long long i1 = i0 + 8LL * ND;
            *(float2*)&Out[i0] = make_float2(acc[mt][nt][0], acc[mt][nt][1]);
            *(float2*)&Out[i1] = make_float2(acc[mt][nt][2], acc[mt][nt][3]);
        }
}

// ---------------- launch ----------------
// Inputs: x [E,T,D] fp32, w1 [E,D,H], w2 [E,H,D], w3 [E,D,H]. Output [E,T,D] fp32.
extern "C" void kernel_launch(void* const* d_in, const int* in_sizes, int n_in,
                              void* d_out, int out_size)
{
    const float* x  = (const float*)d_in[0];
    const float* w1 = (const float*)d_in[1];
    const float* w2 = (const float*)d_in[2];
    const float* w3 = (const float*)d_in[3];
    float* out = (float*)d_out;

    cudaFuncSetAttribute(gemm13_fused, cudaFuncAttributeMaxDynamicSharedMemorySize, 98304);
    cudaFuncSetAttribute(gemm2_out,    cudaFuncAttributeMaxDynamicSharedMemorySize, 98304);

    void *x16, *w1p, *w3p, *w2p, *h16;
    cudaGetSymbolAddress(&x16, g_x16);
    cudaGetSymbolAddress(&w1p, g_w1);
    cudaGetSymbolAddress(&w3p, g_w3);
    cudaGetSymbolAddress(&w2p, g_w2);
    cudaGetSymbolAddress(&h16, g_h16);

    // 1) merged conversion of x, w1, w3 (w2 converted inside gemm13's launch)
    const long long UX = (long long)NE * NT * ND / 8;
    const long long UW = (long long)NE * ND * NH / 8;
    conv3_kernel<<<(int)((UX + 2 * UW) / 256), 256>>>((const float4*)x, (const float4*)w1,
                                                      (const float4*)w3);

    // 2) gemm13 (+ w2 conversion plane at blockIdx.z == NE)
    gemm13_fused<<<dim3(NH / 64, NT / 128, NE + 1), 256, 98304>>>(
        (const __half*)x16, (const __half*)w1p, (const __half*)w3p, (__half*)h16,
        (const float4*)w2);

    // 3) out = h @ w2
    gemm2_out<<<dim3(ND / 128, NT / 128, NE), 256, 98304>>>(
        (const __half*)h16, (const __half*)w2p, out);
}